// round 15
// baseline (speedup 1.0000x reference)
#include <cuda_runtime.h>
#include <cuda_fp16.h>
#include <cstdint>
#include <math.h>

// ---------------- problem constants ----------------
#define B_      2
#define S_      2048
#define DMODEL  2048
#define NH      16
#define DH      128
#define NOPE    14
#define QPROJ   1024
#define KVPROJ  1365
#define KVPAD   1408
#define KNOPE   1792
#define KVCOLS  3840
#define KVLD    4096
#define BS      (B_*S_)
#define NZ      (B_*NH)
#define N1      2688
#define N2      2048

typedef __half h16;

// ---------------- device scratch ----------------
__device__ h16 g_xhi[(size_t)BS*DMODEL];
__device__ h16 g_w1h[(size_t)N1*DMODEL];
__device__ h16 g_w2h[(size_t)N2*QPROJ];
__device__ h16 g_wukvh[(size_t)KVCOLS*KVPAD];
__device__ h16 g_woh[(size_t)DMODEL*DMODEL];
__device__ float g_p1[(size_t)BS*N1];
__device__ h16 g_cqh[(size_t)BS*QPROJ];
__device__ h16 g_ckvh[(size_t)BS*KVPAD];
__device__ h16 g_q2h[(size_t)BS*N2];
__device__ h16 g_kvh[(size_t)BS*KVLD];
__device__ h16 g_aoh[(size_t)BS*DMODEL];

// ---------------- helpers ----------------
__device__ __forceinline__ uint32_t smem_u32(const void* p) {
    uint32_t a;
    asm("{ .reg .u64 t; cvta.to.shared.u64 t, %1; cvt.u32.u64 %0, t; }" : "=r"(a) : "l"(p));
    return a;
}
__device__ __forceinline__ void cp16(uint32_t saddr, const void* g) {
    asm volatile("cp.async.cg.shared.global [%0], [%1], 16;" :: "r"(saddr), "l"(g) : "memory");
}
__device__ __forceinline__ void cp_commit() {
    asm volatile("cp.async.commit_group;" ::: "memory");
}
template<int N> __device__ __forceinline__ void cp_wait() {
    asm volatile("cp.async.wait_group %0;" :: "n"(N) : "memory");
}
__device__ __forceinline__ void ldm_x4(uint32_t addr, uint32_t* r) {
    asm volatile("ldmatrix.sync.aligned.m8n8.x4.shared.b16 {%0,%1,%2,%3}, [%4];"
        : "=r"(r[0]), "=r"(r[1]), "=r"(r[2]), "=r"(r[3]) : "r"(addr));
}
__device__ __forceinline__ void ldm_x4_t(uint32_t addr, uint32_t* r) {
    asm volatile("ldmatrix.sync.aligned.m8n8.x4.trans.shared.b16 {%0,%1,%2,%3}, [%4];"
        : "=r"(r[0]), "=r"(r[1]), "=r"(r[2]), "=r"(r[3]) : "r"(addr));
}
__device__ __forceinline__ void mma16816(float* d, const uint32_t* a, const uint32_t* b) {
    asm volatile("mma.sync.aligned.m16n8k16.row.col.f32.f16.f16.f32 "
        "{%0,%1,%2,%3}, {%4,%5,%6,%7}, {%8,%9}, {%0,%1,%2,%3};"
        : "+f"(d[0]), "+f"(d[1]), "+f"(d[2]), "+f"(d[3])
        : "r"(a[0]), "r"(a[1]), "r"(a[2]), "r"(a[3]), "r"(b[0]), "r"(b[1]));
}
__device__ __forceinline__ uint32_t pack_h2(float a, float b) {
    __half2 t = __floats2half2_rn(a, b);
    return *(uint32_t*)&t;
}

// ---------------- prep device functions ----------------
__device__ __forceinline__ void split_chunk(const float4* __restrict__ in,
                                            __half2* __restrict__ hi,
                                            size_t base4, size_t n4)
{
#pragma unroll
    for (int q = 0; q < 16; q++) {
        size_t i = base4 + (size_t)q * 256 + threadIdx.x;
        if (i >= n4) return;
        float4 v = in[i];
        hi[i * 2]     = __floats2half2_rn(v.x, v.y);
        hi[i * 2 + 1] = __floats2half2_rn(v.z, v.w);
    }
}

__device__ __forceinline__ void tr_strip(const float* __restrict__ in,
                                         h16* __restrict__ hi,
                                         int K, int N, int Npad, int Kpad, int rowOff,
                                         int strip, int nStrips)
{
    __shared__ float t[32][33];
    int kTile = strip / nStrips;
    int nT0 = (strip % nStrips) * 8;
    int k0 = kTile * 32;
    int tx = threadIdx.x & 31, ty = threadIdx.x >> 5;
    for (int sub = 0; sub < 8; sub++) {
        int n0 = (nT0 + sub) * 32;
        if (n0 >= Npad) break;
        __syncthreads();
#pragma unroll
        for (int i = 0; i < 4; i++) {
            int k = k0 + ty + i * 8;
            float v = (k < K && n0 + tx < N) ? in[(size_t)k * N + n0 + tx] : 0.f;
            t[ty + i * 8][tx] = v;
        }
        __syncthreads();
#pragma unroll
        for (int i = 0; i < 4; i++) {
            int n = n0 + ty + i * 8, k = k0 + tx;
            if (n < Npad && k < Kpad)
                hi[(size_t)(n + rowOff) * Kpad + k] = __float2half_rn(t[tx][ty + i * 8]);
        }
    }
}

// rope-K chunk
__device__ __forceinline__ void ropek_chunk(const float* __restrict__ p1,
                                            h16* __restrict__ kvh, int blk)
{
#pragma unroll
    for (int k = 0; k < 8; k++) {
        int e = blk * 2048 + k * 256 + threadIdx.x;
        int dp = e & 63;
        int h2 = (e >> 6) & 1;
        int row = e >> 7;
        int s = row & (S_ - 1);
        float freq = exp2f(-(float)dp * 0.20762050593046015f);
        float sn, cs;
        sincosf((float)s * freq, &sn, &cs);
        const float* src = p1 + (size_t)row * N1 + 2432 + h2 * DH;
        float x1 = src[dp], x2 = src[dp + 64];
        size_t base = (size_t)row * KVLD + KVCOLS + h2 * DH;
        kvh[base + dp]      = __float2half_rn(x1 * cs - x2 * sn);
        kvh[base + dp + 64] = __float2half_rn(x2 * cs + x1 * sn);
    }
}

// ---------------- GEMM core: C = Ah @ Bh^T, BK=64, 3-stage, reg-pipelined -------
#define STAGE 32768
#define SMEM_GEMM (3*STAGE)

__device__ __forceinline__ void gemm_core(
    const h16* __restrict__ Ahi, const h16* __restrict__ Bhi,
    float* __restrict__ Cf, h16* __restrict__ Ch,
    int N, int Kpad, int lda, int ldb, int ldc,
    int r0, int c0, char* smem)
{
    int tid = threadIdx.x, lane = tid & 31, wid = tid >> 5;
    int tiles = Kpad >> 6;

    const h16* Ah = Ahi + (size_t)r0 * lda;
    const h16* Bh = Bhi + (size_t)c0 * ldb;

    uint32_t sbase = smem_u32(smem);
    int wm = (wid >> 2) * 64, wn = (wid & 3) * 32;

    float acc[4][4][4];
#pragma unroll
    for (int i = 0; i < 4; i++)
#pragma unroll
        for (int j = 0; j < 4; j++)
#pragma unroll
            for (int v = 0; v < 4; v++) acc[i][j][v] = 0.f;

    auto load_stage = [&](int t) {
        int k0 = t << 6;
        uint32_t sb = sbase + (uint32_t)(t % 3) * STAGE;
#pragma unroll
        for (int q = 0; q < 4; q++) {
            int idx = tid + q * 256;
            int row = idx >> 3, ch = idx & 7;
            uint32_t off = (uint32_t)row * 128 + (uint32_t)((ch ^ (row & 7)) << 4);
            cp16(sb + off,         Ah + (size_t)row * lda + k0 + ch * 8);
            cp16(sb + 16384 + off, Bh + (size_t)row * ldb + k0 + ch * 8);
        }
        cp_commit();
    };

    auto compute_stage = [&](int t) {
        uint32_t sb = sbase + (uint32_t)(t % 3) * STAGE;

        auto ldB = [&](uint32_t (*bh)[2], int kk) {
#pragma unroll
            for (int p = 0; p < 2; p++) {
                int rowB = wn + p * 16 + ((lane >> 4) << 3) + (lane & 7);
                int ch = (kk >> 3) + ((lane >> 3) & 1);
                uint32_t off = (uint32_t)rowB * 128 + (uint32_t)((ch ^ (rowB & 7)) << 4);
                uint32_t r[4];
                ldm_x4(sb + 16384 + off, r);
                bh[2 * p][0] = r[0]; bh[2 * p][1] = r[1];
                bh[2 * p + 1][0] = r[2]; bh[2 * p + 1][1] = r[3];
            }
        };
        auto ldA = [&](uint32_t* a, int mt, int kk) {
            int rowA = wm + mt * 16 + (lane & 15);
            int ch = (kk >> 3) + (lane >> 4);
            uint32_t off = (uint32_t)rowA * 128 + (uint32_t)((ch ^ (rowA & 7)) << 4);
            ldm_x4(sb + off, a);
        };

        uint32_t b0[4][2], b1[4][2], a0[4], a1[4];
        ldB(b0, 0);
        ldA(a0, 0, 0);
#pragma unroll
        for (int ki = 0; ki < 4; ki++) {
            int kk = ki * 16;
            uint32_t (*bc)[2] = (ki & 1) ? b1 : b0;
            uint32_t (*bn)[2] = (ki & 1) ? b0 : b1;
            if (ki < 3) ldB(bn, kk + 16);
#pragma unroll
            for (int mt = 0; mt < 4; mt++) {
                uint32_t* ac = (mt & 1) ? a1 : a0;
                uint32_t* an = (mt & 1) ? a0 : a1;
                if (mt < 3)      ldA(an, mt + 1, kk);
                else if (ki < 3) ldA(an, 0, kk + 16);
#pragma unroll
                for (int nt = 0; nt < 4; nt++)
                    mma16816(acc[mt][nt], ac, bc[nt]);
            }
        }
    };

    load_stage(0);
    if (tiles > 1) load_stage(1);
    for (int t = 0; t < tiles; t++) {
        if (t + 1 < tiles) cp_wait<1>(); else cp_wait<0>();
        __syncthreads();
        if (t + 2 < tiles) load_stage(t + 2);
        compute_stage(t);
    }

    if (Cf) {
#pragma unroll
        for (int mt = 0; mt < 4; mt++) {
#pragma unroll
            for (int nt = 0; nt < 4; nt++) {
                int r = r0 + wm + mt * 16 + (lane >> 2);
                int c = c0 + wn + nt * 8 + ((lane & 3) << 1);
                float* p0 = Cf + (size_t)r * ldc + c;
                float* p1 = p0 + 8 * ldc;
                p0[0] = acc[mt][nt][0]; p0[1] = acc[mt][nt][1];
                p1[0] = acc[mt][nt][2]; p1[1] = acc[mt][nt][3];
            }
        }
    } else {
#pragma unroll
        for (int mt = 0; mt < 4; mt++) {
#pragma unroll
            for (int nt = 0; nt < 4; nt++) {
                int r = r0 + wm + mt * 16 + (lane >> 2);
                int c = c0 + wn + nt * 8 + ((lane & 3) << 1);
                size_t o0 = (size_t)r * ldc + c;
                size_t o1 = o0 + (size_t)8 * ldc;
                *(uint32_t*)(Ch + o0) = pack_h2(acc[mt][nt][0], acc[mt][nt][1]);
                *(uint32_t*)(Ch + o1) = pack_h2(acc[mt][nt][2], acc[mt][nt][3]);
            }
        }
    }
}

// ---------------- prep1: x convert + W1 transposes ----------------
__global__ __launch_bounds__(256)
void prep1(const float* __restrict__ x,
           const float* __restrict__ W_dq, const float* __restrict__ W_dkv,
           const float* __restrict__ W_kr,
           h16* __restrict__ xhi, h16* __restrict__ w1h)
{
    int i = blockIdx.x;
    if (i < 512) {
        split_chunk((const float4*)x, (__half2*)xhi,
                    (size_t)i * 4096, (size_t)BS * DMODEL / 4);
    } else if (i < 768) {
        tr_strip(W_dq, w1h, DMODEL, QPROJ, QPROJ, DMODEL, 0, i - 512, 4);
    } else if (i < 1152) {
        tr_strip(W_dkv, w1h, DMODEL, KVPROJ, KVPAD, DMODEL, QPROJ, i - 768, 6);
    } else {
        tr_strip(W_kr, w1h, DMODEL, 256, 256, DMODEL, QPROJ + KVPAD, i - 1152, 1);
    }
}

// ---------------- p1 GEMM fused with prep2 ----------------
__global__ __launch_bounds__(256, 2)
void gemm_p1_prep2(const h16* __restrict__ xhi,
                   const h16* __restrict__ w1h,
                   float* __restrict__ p1,
                   const float* __restrict__ W_uq, const float* __restrict__ W_qr,
                   const float* __restrict__ W_ukv, const float* __restrict__ W_o,
                   h16* __restrict__ w2h, h16* __restrict__ wukvh, h16* __restrict__ woh)
{
    extern __shared__ __align__(128) char smem[];
    int i = blockIdx.x;
    bool isGemm;
    int sub;
    if (i < 1344) { isGemm = !(i & 1); sub = i >> 1; }
    else          { isGemm = false;    sub = 672 + (i - 1344); }

    if (isGemm) {
        int cx = sub % 21, cy = sub / 21;
        gemm_core(xhi, w1h, p1, nullptr,
                  N1, DMODEL, DMODEL, DMODEL, N1, cy * 128, cx * 128, smem);
    } else {
        if (sub < 224) {
            tr_strip(W_uq, w2h, QPROJ, KNOPE, KNOPE, QPROJ, 0, sub, 7);
        } else if (sub < 256) {
            tr_strip(W_qr, w2h, QPROJ, 256, 256, QPROJ, KNOPE, sub - 224, 1);
        } else if (sub < 916) {
            tr_strip(W_ukv, wukvh, KVPROJ, KVCOLS, KVCOLS, KVPAD, 0, sub - 256, 15);
        } else {
            split_chunk((const float4*)W_o, (__half2*)woh,
                        (size_t)(sub - 916) * 4096, (size_t)DMODEL * DMODEL / 4);
        }
    }
}

// single GEMM (Wo): fp32 out
__global__ __launch_bounds__(256, 2)
void hmma_gemm1(const h16* __restrict__ Ahi, const h16* __restrict__ Bhi,
                float* __restrict__ Cf, int N, int Kpad, int lda, int ldb, int ldc)
{
    extern __shared__ __align__(128) char smem[];
    gemm_core(Ahi, Bhi, Cf, nullptr, N, Kpad, lda, ldb, ldc,
              blockIdx.y * 128, blockIdx.x * 128, smem);
}

// dual GEMM (q2 + ukv) with rope-K blocks folded in
__global__ __launch_bounds__(256, 2)
void hmma_gemm_dual(
    const h16* A1h, const h16* B1h, h16* C1h,
    int n1, int k1, int la1, int lb1, int lc1, int gx1,
    const h16* A2h, const h16* B2h, h16* C2h,
    int n2, int k2, int la2, int lb2, int lc2, int gx2,
    int split, int total_gemm,
    const float* __restrict__ p1, h16* __restrict__ kvh)
{
    extern __shared__ __align__(128) char smem[];
    int idx = blockIdx.x;
    if (idx >= total_gemm) {
        ropek_chunk(p1, kvh, idx - total_gemm);
        return;
    }
    if (idx < split) {
        int cx = idx % gx1, cy = idx / gx1;
        gemm_core(A1h, B1h, nullptr, C1h, n1, k1, la1, lb1, lc1,
                  cy * 128, cx * 128, smem);
    } else {
        idx -= split;
        int cx = idx % gx2, cy = idx / gx2;
        gemm_core(A2h, B2h, nullptr, C2h, n2, k2, la2, lb2, lc2,
                  cy * 128, cx * 128, smem);
    }
}

// ---------------- fused flash attention (128-key stages, rope-Q fused) ----------
#define FST 65536
#define FQB 32768
#define SMEM_FLASH (FQB + 3*FST)

__global__ __launch_bounds__(256, 1)
void flash_attn(const h16* __restrict__ q2h,
                const h16* __restrict__ kvh,
                h16* __restrict__ aoh)
{
    extern __shared__ __align__(128) char smem[];
    int tid = threadIdx.x, lane = tid & 31, wid = tid >> 5;
    int z = blockIdx.y, bb = z >> 4, hh = z & 15;
    int r0 = ((int)gridDim.x - 1 - (int)blockIdx.x) * 128;

    int kcol = (hh < NOPE) ? hh * DH : KVCOLS + (hh - NOPE) * DH;
    int vcol = KNOPE + hh * DH;

    const h16* qhz = q2h + ((size_t)(bb * S_ + r0)) * N2 + hh * DH;
    const h16* khz = kvh + (size_t)(bb * S_) * KVLD + kcol;
    const h16* vhz = kvh + (size_t)(bb * S_) * KVLD + vcol;

    uint32_t sb = smem_u32(smem);

#pragma unroll
    for (int q = 0; q < 8; q++) {
        int idx = tid + q * 256;
        int row = idx >> 4, ch = idx & 15;
        uint32_t off = (uint32_t)row * 256 + (uint32_t)((ch ^ (row & 7)) << 4);
        cp16(sb + off, qhz + (size_t)row * N2 + ch * 8);
    }
    cp_commit();

    int ntiles = (r0 >> 7) + 1;
    int diag64 = r0 >> 6;

    auto load_stage = [&](int jt) {
        uint32_t st = sb + FQB + (uint32_t)(jt % 3) * FST;
        int s0 = jt * 128;
#pragma unroll
        for (int q = 0; q < 8; q++) {
            int idx = tid + q * 256;
            int row = idx >> 4, ch = idx & 15;
            uint32_t off = (uint32_t)row * 256 + (uint32_t)((ch ^ (row & 7)) << 4);
            size_t g = (size_t)(s0 + row) * KVLD + ch * 8;
            cp16(st + off,         khz + g);
            cp16(st + 32768 + off, vhz + g);
        }
        cp_commit();
    };

    load_stage(0);
    if (ntiles > 1) { load_stage(1); cp_wait<2>(); }
    else            { cp_wait<1>(); }

    if (hh >= NOPE) {
#pragma unroll 4
        for (int k = 0; k < 32; k++) {
            int idx = tid + k * 256;
            int row = idx >> 6, dp = idx & 63;
            float freq = exp2f(-(float)dp * 0.20762050593046015f);
            float sn, cs;
            sincosf((float)(r0 + row) * freq, &sn, &cs);
            uint32_t bin = (uint32_t)(dp & 7) * 2;
            uint32_t ch1 = (uint32_t)(dp >> 3);
            uint32_t o1 = (uint32_t)row * 256 + (((ch1 ^ (row & 7)) << 4) | bin);
            uint32_t o2 = (uint32_t)row * 256 + ((((ch1 + 8) ^ (row & 7)) << 4) | bin);
            float x1 = __half2float(*(h16*)(smem + o1));
            float x2 = __half2float(*(h16*)(smem + o2));
            *(h16*)(smem + o1) = __float2half_rn(x1 * cs - x2 * sn);
            *(h16*)(smem + o2) = __float2half_rn(x2 * cs + x1 * sn);
        }
    }
    __syncthreads();

    int wrow = wid * 16;
    uint32_t qah[8][4];
#pragma unroll
    for (int kf = 0; kf < 8; kf++) {
        int row = wrow + (lane & 15);
        int ch = kf * 2 + (lane >> 4);
        uint32_t off = (uint32_t)row * 256 + (uint32_t)((ch ^ (row & 7)) << 4);
        ldm_x4(sb + off, qah[kf]);
    }

    float of[16][4];
#pragma unroll
    for (int i = 0; i < 16; i++)
#pragma unroll
        for (int v = 0; v < 4; v++) of[i][v] = 0.f;
    float m0 = -1e30f, m1 = -1e30f, l0 = 0.f, l1 = 0.f;
    const float CEXP = 0.08838834764831845f * 1.4426950408889634f;

    int rowa = r0 + wrow + (lane >> 2);

    for (int jt = 0; jt < ntiles; jt++) {
        if (jt + 1 < ntiles) cp_wait<1>(); else cp_wait<0>();
        __syncthreads();
        if (jt + 2 < ntiles) load_stage(jt + 2);
        uint32_t st = sb + FQB + (uint32_t)(jt % 3) * FST;

#pragma unroll
        for (int hf = 0; hf < 2; hf++) {
            int j64 = jt * 2 + hf;
            uint32_t kbase = st + (uint32_t)hf * 16384;
            uint32_t vbase = st + 32768 + (uint32_t)hf * 16384;

            float sf[8][4];
#pragma unroll
            for (int nf = 0; nf < 8; nf++)
#pragma unroll
                for (int v = 0; v < 4; v++) sf[nf][v] = 0.f;

#pragma unroll
            for (int kf = 0; kf < 8; kf++) {
                uint32_t bh[8][2];
#pragma unroll
                for (int p = 0; p < 4; p++) {
                    int rowB = p * 16 + ((lane >> 4) << 3) + (lane & 7);
                    int ch = kf * 2 + ((lane >> 3) & 1);
                    uint32_t off = (uint32_t)rowB * 256 + (uint32_t)((ch ^ (rowB & 7)) << 4);
                    uint32_t r4[4];
                    ldm_x4(kbase + off, r4);
                    bh[2 * p][0] = r4[0]; bh[2 * p][1] = r4[1];
                    bh[2 * p + 1][0] = r4[2]; bh[2 * p + 1][1] = r4[3];
                }
#pragma unroll
                for (int nf = 0; nf < 8; nf++)
                    mma16816(sf[nf], qah[kf], bh[nf]);
            }

            if (j64 >= diag64) {
                int colb = j64 * 64 + 2 * (lane & 3);
#pragma unroll
                for (int nf = 0; nf < 8; nf++) {
                    int c = colb + nf * 8;
                    if (c > rowa)     sf[nf][0] = -1e30f;
                    if (c + 1 > rowa) sf[nf][1] = -1e30f;
                    if (c > rowa + 8)     sf[nf][2] = -1e30f;
                    if (c + 1 > rowa + 8) sf[nf][3] = -1e30f;
                }
            }

            float tm0 = -1e30f, tm1 = -1e30f;
#pragma unroll
            for (int nf = 0; nf < 8; nf++) {
                tm0 = fmaxf(tm0, fmaxf(sf[nf][0], sf[nf][1]));
                tm1 = fmaxf(tm1, fmaxf(sf[nf][2], sf[nf][3]));
            }
            tm0 = fmaxf(tm0, __shfl_xor_sync(0xffffffffu, tm0, 1));
            tm0 = fmaxf(tm0, __shfl_xor_sync(0xffffffffu, tm0, 2));
            tm1 = fmaxf(tm1, __shfl_xor_sync(0xffffffffu, tm1, 1));
            tm1 = fmaxf(tm1, __shfl_xor_sync(0xffffffffu, tm1, 2));
            float mn0 = fmaxf(m0, tm0), mn1 = fmaxf(m1, tm1);
            bool changed = (mn0 != m0) || (mn1 != m1);
            float al0 = 1.f, al1 = 1.f;
            if (changed) {
                al0 = exp2f((m0 - mn0) * CEXP);
                al1 = exp2f((m1 - mn1) * CEXP);
                m0 = mn0; m1 = mn1;
            }

            uint32_t pah[4][4];
            float rs0 = 0.f, rs1 = 0.f;
#pragma unroll
            for (int nf = 0; nf < 8; nf++) {
                float e0 = exp2f((sf[nf][0] - m0) * CEXP);
                float e1 = exp2f((sf[nf][1] - m0) * CEXP);
                float e2 = exp2f((sf[nf][2] - m1) * CEXP);
                float e3 = exp2f((sf[nf][3] - m1) * CEXP);
                rs0 += e0 + e1; rs1 += e2 + e3;
                int kf2 = nf >> 1, s = (nf & 1) * 2;
                pah[kf2][s]     = pack_h2(e0, e1);
                pah[kf2][s + 1] = pack_h2(e2, e3);
            }
            l0 = l0 * al0 + rs0;
            l1 = l1 * al1 + rs1;

            if (changed) {
#pragma unroll
                for (int i = 0; i < 16; i++) {
                    of[i][0] *= al0; of[i][1] *= al0;
                    of[i][2] *= al1; of[i][3] *= al1;
                }
            }

#pragma unroll
            for (int kf2 = 0; kf2 < 4; kf2++) {
#pragma unroll
                for (int nb = 0; nb < 8; nb++) {
                    int row = kf2 * 16 + (lane & 15);
                    int ch = nb * 2 + (lane >> 4);
                    uint32_t off = (uint32_t)row * 256 + (uint32_t)((ch ^ (row & 7)) << 4);
                    uint32_t rh[4];
                    ldm_x4_t(vbase + off, rh);
                    uint32_t bh0[2] = {rh[0], rh[1]}, bh1[2] = {rh[2], rh[3]};
                    mma16816(of[2 * nb],     pah[kf2], bh0);
                    mma16816(of[2 * nb + 1], pah[kf2], bh1);
                }
            }
        }
    }

    l0 += __shfl_xor_sync(0xffffffffu, l0, 1);
    l0 += __shfl_xor_sync(0xffffffffu, l0, 2);
    l1 += __shfl_xor_sync(0xffffffffu, l1, 1);
    l1 += __shfl_xor_sync(0xffffffffu, l1, 2);
    float inv0 = 1.f / l0, inv1 = 1.f / l1;

    size_t ga = ((size_t)(bb * S_) + rowa) * DMODEL + hh * DH;
    size_t gb = ga + (size_t)8 * DMODEL;
#pragma unroll
    for (int i = 0; i < 16; i++) {
        int d = i * 8 + 2 * (lane & 3);
        *(uint32_t*)(aoh + ga + d) = pack_h2(of[i][0] * inv0, of[i][1] * inv0);
        *(uint32_t*)(aoh + gb + d) = pack_h2(of[i][2] * inv1, of[i][3] * inv1);
    }
}

// ---------------- merged LayerNorm ----------------
__global__ __launch_bounds__(256)
void layernorm2(const float* __restrict__ p1,
                h16* __restrict__ cqh,
                float* __restrict__ ckv,
                h16* __restrict__ ckvh,
                const float* __restrict__ q_w, const float* __restrict__ q_b,
                const float* __restrict__ kv_w, const float* __restrict__ kv_b)
{
    bool isKV = blockIdx.y != 0;
    const float* p = p1 + (size_t)blockIdx.x * N1 + (isKV ? QPROJ : 0);
    int n = isKV ? KVPROJ : QPROJ;
    int npad = isKV ? KVPAD : QPROJ;
    const float* w = isKV ? kv_w : q_w;
    const float* b = isKV ? kv_b : q_b;
    h16* hh = (isKV ? ckvh : cqh) + (size_t)blockIdx.x * npad;
    float* of = isKV ? ckv + (size_t)blockIdx.x * KVPROJ : nullptr;

    float s = 0.f, s2 = 0.f;
    for (int j = threadIdx.x; j < n; j += 256) {
        float v = p[j];
        s += v; s2 += v * v;
    }
    __shared__ float sh[20];
#pragma unroll
    for (int o = 16; o; o >>= 1) {
        s  += __shfl_down_sync(0xffffffffu, s,  o);
        s2 += __shfl_down_sync(0xffffffffu, s2, o);
    }
    int wd = threadIdx.x >> 5, ln = threadIdx.x & 31;
    if (!ln) { sh[wd] = s; sh[wd + 8] = s2; }
    __syncthreads();
    if (threadIdx.x == 0) {
        float ts = 0.f, ts2 = 0.f;
        for (int i = 0; i < 8; i++) { ts += sh[i]; ts2 += sh[i + 8]; }
        float mean = ts / n;
        float var = fmaxf(ts2 / n - mean * mean, 0.f);
        sh[16] = mean;
        sh[17] = rsqrtf(var + 1e-5f);
    }
    __syncthreads();
    float mean = sh[16], rstd = sh[17];
    for (int j = threadIdx.x; j < npad; j += 256) {
        float v = 0.f;
        if (j < n) {
            v = (p[j] - mean) * rstd * w[j] + b[j];
            if (of) of[j] = v;
        }
        hh[j] = __float2half_rn(v);
    }
}

// ---------------- launch ----------------
static inline void* sym(const void* s) { void* p; cudaGetSymbolAddress(&p, s); return p; }

extern "C" void kernel_launch(void* const* d_in, const int* in_sizes, int n_in,
                              void* d_out, int out_size)
{
    const float* x     = (const float*)d_in[0];
    const float* W_dq  = (const float*)d_in[1];
    const float* W_uq  = (const float*)d_in[2];
    const float* W_qr  = (const float*)d_in[3];
    const float* W_dkv = (const float*)d_in[4];
    const float* W_ukv = (const float*)d_in[5];
    const float* W_kr  = (const float*)d_in[6];
    const float* W_o   = (const float*)d_in[7];
    const float* q_w   = (const float*)d_in[8];
    const float* q_b   = (const float*)d_in[9];
    const float* kv_w  = (const float*)d_in[10];
    const float* kv_b  = (const float*)d_in[11];

    float* out = (float*)d_out;
    float* ckv = out + (size_t)BS * DMODEL;

    h16 *xhi=(h16*)sym(g_xhi);
    h16 *w1h=(h16*)sym(g_w1h);
    h16 *w2h=(h16*)sym(g_w2h);
    h16 *wukvh=(h16*)sym(g_wukvh);
    h16 *woh=(h16*)sym(g_woh);
    float *p1=(float*)sym(g_p1);
    h16 *cqh=(h16*)sym(g_cqh);
    h16 *ckvh=(h16*)sym(g_ckvh);
    h16 *q2h=(h16*)sym(g_q2h);
    h16 *kvh=(h16*)sym(g_kvh);
    h16 *aoh=(h16*)sym(g_aoh);

    cudaFuncSetAttribute(hmma_gemm1, cudaFuncAttributeMaxDynamicSharedMemorySize, SMEM_GEMM);
    cudaFuncSetAttribute(hmma_gemm_dual, cudaFuncAttributeMaxDynamicSharedMemorySize, SMEM_GEMM);
    cudaFuncSetAttribute(gemm_p1_prep2, cudaFuncAttributeMaxDynamicSharedMemorySize, SMEM_GEMM);
    cudaFuncSetAttribute(flash_attn, cudaFuncAttributeMaxDynamicSharedMemorySize, SMEM_FLASH);

    // 1. x convert + W1 transposes
    prep1<<<1216, 256>>>(x, W_dq, W_dkv, W_kr, xhi, w1h);

    // 2. p1 = x @ W1 (fp32) fused with prep2
    gemm_p1_prep2<<<1844, 256, SMEM_GEMM>>>(
        xhi, w1h, p1,
        W_uq, W_qr, W_ukv, W_o,
        w2h, wukvh, woh);

    // 3. LayerNorms (merged)
    layernorm2<<<dim3(BS, 2), 256>>>(p1, cqh, ckv, ckvh, q_w, q_b, kv_w, kv_b);

    // 4. q2 + ukv GEMMs + rope-K in one launch
    {
        int gx_ukv = KVCOLS / 128;              // 30
        int gx_q2  = N2 / 128;                  // 16
        int blocks_ukv = gx_ukv * (BS / 128);   // 960
        int blocks_q2  = gx_q2  * (BS / 128);   // 512
        int total_gemm = blocks_ukv + blocks_q2;
        hmma_gemm_dual<<<total_gemm + 256, 256, SMEM_GEMM>>>(
            ckvh, wukvh, kvh,
            KVCOLS, KVPAD, KVPAD, KVPAD, KVLD, gx_ukv,
            cqh, w2h, q2h,
            N2, QPROJ, QPROJ, QPROJ, N2, gx_q2,
            blocks_ukv, total_gemm,
            p1, kvh);
    }

    // 5. flash attention (rope-Q fused in prologue)
    flash_attn<<<dim3(S_/128, NZ), 256, SMEM_FLASH>>>(q2h, kvh, aoh);

    // 6. final projection
    hmma_gemm1<<<dim3(DMODEL/128, BS/128), 256, SMEM_GEMM>>>(
        aoh, woh, out, DMODEL, DMODEL, DMODEL, DMODEL, DMODEL);
}

// round 16
// speedup vs baseline: 1.0197x; 1.0197x over previous
#include <cuda_runtime.h>
#include <cuda_fp16.h>
#include <cstdint>
#include <math.h>

// ---------------- problem constants ----------------
#define B_      2
#define S_      2048
#define DMODEL  2048
#define NH      16
#define DH      128
#define NOPE    14
#define QPROJ   1024
#define KVPROJ  1365
#define KVPAD   1408
#define KNOPE   1792
#define KVCOLS  3840
#define KVLD    4096
#define BS      (B_*S_)
#define NZ      (B_*NH)
#define N1      2688
#define N2      2048

typedef __half h16;

// ---------------- device scratch ----------------
__device__ h16 g_xhi[(size_t)BS*DMODEL];
__device__ h16 g_w1h[(size_t)N1*DMODEL];
__device__ h16 g_w2h[(size_t)N2*QPROJ];
__device__ h16 g_wukvh[(size_t)KVCOLS*KVPAD];
__device__ h16 g_woh[(size_t)DMODEL*DMODEL];
__device__ float g_p1[(size_t)BS*N1];
__device__ h16 g_cqh[(size_t)BS*QPROJ];
__device__ h16 g_ckvh[(size_t)BS*KVPAD];
__device__ h16 g_q2h[(size_t)BS*N2];
__device__ h16 g_kvh[(size_t)BS*KVLD];
__device__ h16 g_aoh[(size_t)BS*DMODEL];

// ---------------- helpers ----------------
__device__ __forceinline__ uint32_t smem_u32(const void* p) {
    uint32_t a;
    asm("{ .reg .u64 t; cvta.to.shared.u64 t, %1; cvt.u32.u64 %0, t; }" : "=r"(a) : "l"(p));
    return a;
}
__device__ __forceinline__ void cp16(uint32_t saddr, const void* g) {
    asm volatile("cp.async.cg.shared.global [%0], [%1], 16;" :: "r"(saddr), "l"(g) : "memory");
}
__device__ __forceinline__ void cp_commit() {
    asm volatile("cp.async.commit_group;" ::: "memory");
}
template<int N> __device__ __forceinline__ void cp_wait() {
    asm volatile("cp.async.wait_group %0;" :: "n"(N) : "memory");
}
__device__ __forceinline__ void ldm_x4(uint32_t addr, uint32_t* r) {
    asm volatile("ldmatrix.sync.aligned.m8n8.x4.shared.b16 {%0,%1,%2,%3}, [%4];"
        : "=r"(r[0]), "=r"(r[1]), "=r"(r[2]), "=r"(r[3]) : "r"(addr));
}
__device__ __forceinline__ void ldm_x4_t(uint32_t addr, uint32_t* r) {
    asm volatile("ldmatrix.sync.aligned.m8n8.x4.trans.shared.b16 {%0,%1,%2,%3}, [%4];"
        : "=r"(r[0]), "=r"(r[1]), "=r"(r[2]), "=r"(r[3]) : "r"(addr));
}
__device__ __forceinline__ void mma16816(float* d, const uint32_t* a, const uint32_t* b) {
    asm volatile("mma.sync.aligned.m16n8k16.row.col.f32.f16.f16.f32 "
        "{%0,%1,%2,%3}, {%4,%5,%6,%7}, {%8,%9}, {%0,%1,%2,%3};"
        : "+f"(d[0]), "+f"(d[1]), "+f"(d[2]), "+f"(d[3])
        : "r"(a[0]), "r"(a[1]), "r"(a[2]), "r"(a[3]), "r"(b[0]), "r"(b[1]));
}
__device__ __forceinline__ uint32_t pack_h2(float a, float b) {
    __half2 t = __floats2half2_rn(a, b);
    return *(uint32_t*)&t;
}

// ---------------- prep device functions ----------------
__device__ __forceinline__ void split_chunk(const float4* __restrict__ in,
                                            __half2* __restrict__ hi,
                                            size_t base4, size_t n4)
{
#pragma unroll
    for (int q = 0; q < 16; q++) {
        size_t i = base4 + (size_t)q * 256 + threadIdx.x;
        if (i >= n4) return;
        float4 v = in[i];
        hi[i * 2]     = __floats2half2_rn(v.x, v.y);
        hi[i * 2 + 1] = __floats2half2_rn(v.z, v.w);
    }
}

__device__ __forceinline__ void tr_strip(const float* __restrict__ in,
                                         h16* __restrict__ hi,
                                         int K, int N, int Npad, int Kpad, int rowOff,
                                         int strip, int nStrips)
{
    __shared__ float t[32][33];
    int kTile = strip / nStrips;
    int nT0 = (strip % nStrips) * 8;
    int k0 = kTile * 32;
    int tx = threadIdx.x & 31, ty = threadIdx.x >> 5;
    for (int sub = 0; sub < 8; sub++) {
        int n0 = (nT0 + sub) * 32;
        if (n0 >= Npad) break;
        __syncthreads();
#pragma unroll
        for (int i = 0; i < 4; i++) {
            int k = k0 + ty + i * 8;
            float v = (k < K && n0 + tx < N) ? in[(size_t)k * N + n0 + tx] : 0.f;
            t[ty + i * 8][tx] = v;
        }
        __syncthreads();
#pragma unroll
        for (int i = 0; i < 4; i++) {
            int n = n0 + ty + i * 8, k = k0 + tx;
            if (n < Npad && k < Kpad)
                hi[(size_t)(n + rowOff) * Kpad + k] = __float2half_rn(t[tx][ty + i * 8]);
        }
    }
}

// rope-K chunk
__device__ __forceinline__ void ropek_chunk(const float* __restrict__ p1,
                                            h16* __restrict__ kvh, int blk)
{
#pragma unroll
    for (int k = 0; k < 8; k++) {
        int e = blk * 2048 + k * 256 + threadIdx.x;
        int dp = e & 63;
        int h2 = (e >> 6) & 1;
        int row = e >> 7;
        int s = row & (S_ - 1);
        float freq = exp2f(-(float)dp * 0.20762050593046015f);
        float sn, cs;
        sincosf((float)s * freq, &sn, &cs);
        const float* src = p1 + (size_t)row * N1 + 2432 + h2 * DH;
        float x1 = src[dp], x2 = src[dp + 64];
        size_t base = (size_t)row * KVLD + KVCOLS + h2 * DH;
        kvh[base + dp]      = __float2half_rn(x1 * cs - x2 * sn);
        kvh[base + dp + 64] = __float2half_rn(x2 * cs + x1 * sn);
    }
}

// ---------------- GEMM core: C = Ah @ Bh^T, BK=64, 3-stage, reg-pipelined -------
#define STAGE 32768
#define SMEM_GEMM (3*STAGE)

__device__ __forceinline__ void gemm_core(
    const h16* __restrict__ Ahi, const h16* __restrict__ Bhi,
    float* __restrict__ Cf, h16* __restrict__ Ch,
    int N, int Kpad, int lda, int ldb, int ldc,
    int r0, int c0, char* smem)
{
    int tid = threadIdx.x, lane = tid & 31, wid = tid >> 5;
    int tiles = Kpad >> 6;

    const h16* Ah = Ahi + (size_t)r0 * lda;
    const h16* Bh = Bhi + (size_t)c0 * ldb;

    uint32_t sbase = smem_u32(smem);
    int wm = (wid >> 2) * 64, wn = (wid & 3) * 32;

    float acc[4][4][4];
#pragma unroll
    for (int i = 0; i < 4; i++)
#pragma unroll
        for (int j = 0; j < 4; j++)
#pragma unroll
            for (int v = 0; v < 4; v++) acc[i][j][v] = 0.f;

    auto load_stage = [&](int t) {
        int k0 = t << 6;
        uint32_t sb = sbase + (uint32_t)(t % 3) * STAGE;
#pragma unroll
        for (int q = 0; q < 4; q++) {
            int idx = tid + q * 256;
            int row = idx >> 3, ch = idx & 7;
            uint32_t off = (uint32_t)row * 128 + (uint32_t)((ch ^ (row & 7)) << 4);
            cp16(sb + off,         Ah + (size_t)row * lda + k0 + ch * 8);
            cp16(sb + 16384 + off, Bh + (size_t)row * ldb + k0 + ch * 8);
        }
        cp_commit();
    };

    auto compute_stage = [&](int t) {
        uint32_t sb = sbase + (uint32_t)(t % 3) * STAGE;

        auto ldB = [&](uint32_t (*bh)[2], int kk) {
#pragma unroll
            for (int p = 0; p < 2; p++) {
                int rowB = wn + p * 16 + ((lane >> 4) << 3) + (lane & 7);
                int ch = (kk >> 3) + ((lane >> 3) & 1);
                uint32_t off = (uint32_t)rowB * 128 + (uint32_t)((ch ^ (rowB & 7)) << 4);
                uint32_t r[4];
                ldm_x4(sb + 16384 + off, r);
                bh[2 * p][0] = r[0]; bh[2 * p][1] = r[1];
                bh[2 * p + 1][0] = r[2]; bh[2 * p + 1][1] = r[3];
            }
        };
        auto ldA = [&](uint32_t* a, int mt, int kk) {
            int rowA = wm + mt * 16 + (lane & 15);
            int ch = (kk >> 3) + (lane >> 4);
            uint32_t off = (uint32_t)rowA * 128 + (uint32_t)((ch ^ (rowA & 7)) << 4);
            ldm_x4(sb + off, a);
        };

        uint32_t b0[4][2], b1[4][2], a0[4], a1[4];
        ldB(b0, 0);
        ldA(a0, 0, 0);
#pragma unroll
        for (int ki = 0; ki < 4; ki++) {
            int kk = ki * 16;
            uint32_t (*bc)[2] = (ki & 1) ? b1 : b0;
            uint32_t (*bn)[2] = (ki & 1) ? b0 : b1;
            if (ki < 3) ldB(bn, kk + 16);
#pragma unroll
            for (int mt = 0; mt < 4; mt++) {
                uint32_t* ac = (mt & 1) ? a1 : a0;
                uint32_t* an = (mt & 1) ? a0 : a1;
                if (mt < 3)      ldA(an, mt + 1, kk);
                else if (ki < 3) ldA(an, 0, kk + 16);
#pragma unroll
                for (int nt = 0; nt < 4; nt++)
                    mma16816(acc[mt][nt], ac, bc[nt]);
            }
        }
    };

    load_stage(0);
    if (tiles > 1) load_stage(1);
    for (int t = 0; t < tiles; t++) {
        if (t + 1 < tiles) cp_wait<1>(); else cp_wait<0>();
        __syncthreads();
        if (t + 2 < tiles) load_stage(t + 2);
        compute_stage(t);
    }

    if (Cf) {
#pragma unroll
        for (int mt = 0; mt < 4; mt++) {
#pragma unroll
            for (int nt = 0; nt < 4; nt++) {
                int r = r0 + wm + mt * 16 + (lane >> 2);
                int c = c0 + wn + nt * 8 + ((lane & 3) << 1);
                float* p0 = Cf + (size_t)r * ldc + c;
                float* p1 = p0 + 8 * ldc;
                p0[0] = acc[mt][nt][0]; p0[1] = acc[mt][nt][1];
                p1[0] = acc[mt][nt][2]; p1[1] = acc[mt][nt][3];
            }
        }
    } else {
#pragma unroll
        for (int mt = 0; mt < 4; mt++) {
#pragma unroll
            for (int nt = 0; nt < 4; nt++) {
                int r = r0 + wm + mt * 16 + (lane >> 2);
                int c = c0 + wn + nt * 8 + ((lane & 3) << 1);
                size_t o0 = (size_t)r * ldc + c;
                size_t o1 = o0 + (size_t)8 * ldc;
                *(uint32_t*)(Ch + o0) = pack_h2(acc[mt][nt][0], acc[mt][nt][1]);
                *(uint32_t*)(Ch + o1) = pack_h2(acc[mt][nt][2], acc[mt][nt][3]);
            }
        }
    }
}

// ---------------- prep1: x convert + W1 transposes ----------------
__global__ __launch_bounds__(256)
void prep1(const float* __restrict__ x,
           const float* __restrict__ W_dq, const float* __restrict__ W_dkv,
           const float* __restrict__ W_kr,
           h16* __restrict__ xhi, h16* __restrict__ w1h)
{
    int i = blockIdx.x;
    if (i < 512) {
        split_chunk((const float4*)x, (__half2*)xhi,
                    (size_t)i * 4096, (size_t)BS * DMODEL / 4);
    } else if (i < 768) {
        tr_strip(W_dq, w1h, DMODEL, QPROJ, QPROJ, DMODEL, 0, i - 512, 4);
    } else if (i < 1152) {
        tr_strip(W_dkv, w1h, DMODEL, KVPROJ, KVPAD, DMODEL, QPROJ, i - 768, 6);
    } else {
        tr_strip(W_kr, w1h, DMODEL, 256, 256, DMODEL, QPROJ + KVPAD, i - 1152, 1);
    }
}

// ---------------- p1 GEMM fused with prep2 ----------------
__global__ __launch_bounds__(256, 2)
void gemm_p1_prep2(const h16* __restrict__ xhi,
                   const h16* __restrict__ w1h,
                   float* __restrict__ p1,
                   const float* __restrict__ W_uq, const float* __restrict__ W_qr,
                   const float* __restrict__ W_ukv, const float* __restrict__ W_o,
                   h16* __restrict__ w2h, h16* __restrict__ wukvh, h16* __restrict__ woh)
{
    extern __shared__ __align__(128) char smem[];
    int i = blockIdx.x;
    bool isGemm;
    int sub;
    if (i < 1344) { isGemm = !(i & 1); sub = i >> 1; }
    else          { isGemm = false;    sub = 672 + (i - 1344); }

    if (isGemm) {
        int cx = sub % 21, cy = sub / 21;
        gemm_core(xhi, w1h, p1, nullptr,
                  N1, DMODEL, DMODEL, DMODEL, N1, cy * 128, cx * 128, smem);
    } else {
        if (sub < 224) {
            tr_strip(W_uq, w2h, QPROJ, KNOPE, KNOPE, QPROJ, 0, sub, 7);
        } else if (sub < 256) {
            tr_strip(W_qr, w2h, QPROJ, 256, 256, QPROJ, KNOPE, sub - 224, 1);
        } else if (sub < 916) {
            tr_strip(W_ukv, wukvh, KVPROJ, KVCOLS, KVCOLS, KVPAD, 0, sub - 256, 15);
        } else {
            split_chunk((const float4*)W_o, (__half2*)woh,
                        (size_t)(sub - 916) * 4096, (size_t)DMODEL * DMODEL / 4);
        }
    }
}

// single GEMM (Wo): fp32 out
__global__ __launch_bounds__(256, 2)
void hmma_gemm1(const h16* __restrict__ Ahi, const h16* __restrict__ Bhi,
                float* __restrict__ Cf, int N, int Kpad, int lda, int ldb, int ldc)
{
    extern __shared__ __align__(128) char smem[];
    gemm_core(Ahi, Bhi, Cf, nullptr, N, Kpad, lda, ldb, ldc,
              blockIdx.y * 128, blockIdx.x * 128, smem);
}

// dual GEMM (q2 + ukv) with rope-K blocks folded in
__global__ __launch_bounds__(256, 2)
void hmma_gemm_dual(
    const h16* A1h, const h16* B1h, h16* C1h,
    int n1, int k1, int la1, int lb1, int lc1, int gx1,
    const h16* A2h, const h16* B2h, h16* C2h,
    int n2, int k2, int la2, int lb2, int lc2, int gx2,
    int split, int total_gemm,
    const float* __restrict__ p1, h16* __restrict__ kvh)
{
    extern __shared__ __align__(128) char smem[];
    int idx = blockIdx.x;
    if (idx >= total_gemm) {
        ropek_chunk(p1, kvh, idx - total_gemm);
        return;
    }
    if (idx < split) {
        int cx = idx % gx1, cy = idx / gx1;
        gemm_core(A1h, B1h, nullptr, C1h, n1, k1, la1, lb1, lc1,
                  cy * 128, cx * 128, smem);
    } else {
        idx -= split;
        int cx = idx % gx2, cy = idx / gx2;
        gemm_core(A2h, B2h, nullptr, C2h, n2, k2, la2, lb2, lc2,
                  cy * 128, cx * 128, smem);
    }
}

// ---------------- fused flash attention (128-key stages, rope-Q fused) ----------
#define FST 65536
#define FQB 32768
#define SMEM_FLASH (FQB + 3*FST)

__global__ __launch_bounds__(256, 1)
void flash_attn(const h16* __restrict__ q2h,
                const h16* __restrict__ kvh,
                h16* __restrict__ aoh)
{
    extern __shared__ __align__(128) char smem[];
    int tid = threadIdx.x, lane = tid & 31, wid = tid >> 5;
    int z = blockIdx.y, bb = z >> 4, hh = z & 15;
    int r0 = ((int)gridDim.x - 1 - (int)blockIdx.x) * 128;

    int kcol = (hh < NOPE) ? hh * DH : KVCOLS + (hh - NOPE) * DH;
    int vcol = KNOPE + hh * DH;

    const h16* qhz = q2h + ((size_t)(bb * S_ + r0)) * N2 + hh * DH;
    const h16* khz = kvh + (size_t)(bb * S_) * KVLD + kcol;
    const h16* vhz = kvh + (size_t)(bb * S_) * KVLD + vcol;

    uint32_t sb = smem_u32(smem);

#pragma unroll
    for (int q = 0; q < 8; q++) {
        int idx = tid + q * 256;
        int row = idx >> 4, ch = idx & 15;
        uint32_t off = (uint32_t)row * 256 + (uint32_t)((ch ^ (row & 7)) << 4);
        cp16(sb + off, qhz + (size_t)row * N2 + ch * 8);
    }
    cp_commit();

    int ntiles = (r0 >> 7) + 1;
    int diag64 = r0 >> 6;

    auto load_stage = [&](int jt) {
        uint32_t st = sb + FQB + (uint32_t)(jt % 3) * FST;
        int s0 = jt * 128;
#pragma unroll
        for (int q = 0; q < 8; q++) {
            int idx = tid + q * 256;
            int row = idx >> 4, ch = idx & 15;
            uint32_t off = (uint32_t)row * 256 + (uint32_t)((ch ^ (row & 7)) << 4);
            size_t g = (size_t)(s0 + row) * KVLD + ch * 8;
            cp16(st + off,         khz + g);
            cp16(st + 32768 + off, vhz + g);
        }
        cp_commit();
    };

    load_stage(0);
    if (ntiles > 1) { load_stage(1); cp_wait<2>(); }
    else            { cp_wait<1>(); }

    if (hh >= NOPE) {
#pragma unroll 4
        for (int k = 0; k < 32; k++) {
            int idx = tid + k * 256;
            int row = idx >> 6, dp = idx & 63;
            float freq = exp2f(-(float)dp * 0.20762050593046015f);
            float sn, cs;
            sincosf((float)(r0 + row) * freq, &sn, &cs);
            uint32_t bin = (uint32_t)(dp & 7) * 2;
            uint32_t ch1 = (uint32_t)(dp >> 3);
            uint32_t o1 = (uint32_t)row * 256 + (((ch1 ^ (row & 7)) << 4) | bin);
            uint32_t o2 = (uint32_t)row * 256 + ((((ch1 + 8) ^ (row & 7)) << 4) | bin);
            float x1 = __half2float(*(h16*)(smem + o1));
            float x2 = __half2float(*(h16*)(smem + o2));
            *(h16*)(smem + o1) = __float2half_rn(x1 * cs - x2 * sn);
            *(h16*)(smem + o2) = __float2half_rn(x2 * cs + x1 * sn);
        }
    }
    __syncthreads();

    int wrow = wid * 16;
    uint32_t qah[8][4];
#pragma unroll
    for (int kf = 0; kf < 8; kf++) {
        int row = wrow + (lane & 15);
        int ch = kf * 2 + (lane >> 4);
        uint32_t off = (uint32_t)row * 256 + (uint32_t)((ch ^ (row & 7)) << 4);
        ldm_x4(sb + off, qah[kf]);
    }

    float of[16][4];
#pragma unroll
    for (int i = 0; i < 16; i++)
#pragma unroll
        for (int v = 0; v < 4; v++) of[i][v] = 0.f;
    float m0 = -1e30f, m1 = -1e30f, l0 = 0.f, l1 = 0.f;
    const float CEXP = 0.08838834764831845f * 1.4426950408889634f;

    int rowa = r0 + wrow + (lane >> 2);

    for (int jt = 0; jt < ntiles; jt++) {
        if (jt + 1 < ntiles) cp_wait<1>(); else cp_wait<0>();
        __syncthreads();
        if (jt + 2 < ntiles) load_stage(jt + 2);
        uint32_t st = sb + FQB + (uint32_t)(jt % 3) * FST;

#pragma unroll
        for (int hf = 0; hf < 2; hf++) {
            int j64 = jt * 2 + hf;
            uint32_t kbase = st + (uint32_t)hf * 16384;
            uint32_t vbase = st + 32768 + (uint32_t)hf * 16384;

            float sf[8][4];
#pragma unroll
            for (int nf = 0; nf < 8; nf++)
#pragma unroll
                for (int v = 0; v < 4; v++) sf[nf][v] = 0.f;

#pragma unroll
            for (int kf = 0; kf < 8; kf++) {
                uint32_t bh[8][2];
#pragma unroll
                for (int p = 0; p < 4; p++) {
                    int rowB = p * 16 + ((lane >> 4) << 3) + (lane & 7);
                    int ch = kf * 2 + ((lane >> 3) & 1);
                    uint32_t off = (uint32_t)rowB * 256 + (uint32_t)((ch ^ (rowB & 7)) << 4);
                    uint32_t r4[4];
                    ldm_x4(kbase + off, r4);
                    bh[2 * p][0] = r4[0]; bh[2 * p][1] = r4[1];
                    bh[2 * p + 1][0] = r4[2]; bh[2 * p + 1][1] = r4[3];
                }
#pragma unroll
                for (int nf = 0; nf < 8; nf++)
                    mma16816(sf[nf], qah[kf], bh[nf]);
            }

            if (j64 >= diag64) {
                int colb = j64 * 64 + 2 * (lane & 3);
#pragma unroll
                for (int nf = 0; nf < 8; nf++) {
                    int c = colb + nf * 8;
                    if (c > rowa)     sf[nf][0] = -1e30f;
                    if (c + 1 > rowa) sf[nf][1] = -1e30f;
                    if (c > rowa + 8)     sf[nf][2] = -1e30f;
                    if (c + 1 > rowa + 8) sf[nf][3] = -1e30f;
                }
            }

            float tm0 = -1e30f, tm1 = -1e30f;
#pragma unroll
            for (int nf = 0; nf < 8; nf++) {
                tm0 = fmaxf(tm0, fmaxf(sf[nf][0], sf[nf][1]));
                tm1 = fmaxf(tm1, fmaxf(sf[nf][2], sf[nf][3]));
            }
            tm0 = fmaxf(tm0, __shfl_xor_sync(0xffffffffu, tm0, 1));
            tm0 = fmaxf(tm0, __shfl_xor_sync(0xffffffffu, tm0, 2));
            tm1 = fmaxf(tm1, __shfl_xor_sync(0xffffffffu, tm1, 1));
            tm1 = fmaxf(tm1, __shfl_xor_sync(0xffffffffu, tm1, 2));
            float mn0 = fmaxf(m0, tm0), mn1 = fmaxf(m1, tm1);
            float al0 = exp2f((m0 - mn0) * CEXP), al1 = exp2f((m1 - mn1) * CEXP);
            m0 = mn0; m1 = mn1;

            uint32_t pah[4][4];
            float rs0 = 0.f, rs1 = 0.f;
#pragma unroll
            for (int nf = 0; nf < 8; nf++) {
                float e0 = exp2f((sf[nf][0] - m0) * CEXP);
                float e1 = exp2f((sf[nf][1] - m0) * CEXP);
                float e2 = exp2f((sf[nf][2] - m1) * CEXP);
                float e3 = exp2f((sf[nf][3] - m1) * CEXP);
                rs0 += e0 + e1; rs1 += e2 + e3;
                int kf2 = nf >> 1, s = (nf & 1) * 2;
                pah[kf2][s]     = pack_h2(e0, e1);
                pah[kf2][s + 1] = pack_h2(e2, e3);
            }
            l0 = l0 * al0 + rs0;
            l1 = l1 * al1 + rs1;

#pragma unroll
            for (int i = 0; i < 16; i++) {
                of[i][0] *= al0; of[i][1] *= al0;
                of[i][2] *= al1; of[i][3] *= al1;
            }

#pragma unroll
            for (int kf2 = 0; kf2 < 4; kf2++) {
#pragma unroll
                for (int nb = 0; nb < 8; nb++) {
                    int row = kf2 * 16 + (lane & 15);
                    int ch = nb * 2 + (lane >> 4);
                    uint32_t off = (uint32_t)row * 256 + (uint32_t)((ch ^ (row & 7)) << 4);
                    uint32_t rh[4];
                    ldm_x4_t(vbase + off, rh);
                    uint32_t bh0[2] = {rh[0], rh[1]}, bh1[2] = {rh[2], rh[3]};
                    mma16816(of[2 * nb],     pah[kf2], bh0);
                    mma16816(of[2 * nb + 1], pah[kf2], bh1);
                }
            }
        }
    }

    l0 += __shfl_xor_sync(0xffffffffu, l0, 1);
    l0 += __shfl_xor_sync(0xffffffffu, l0, 2);
    l1 += __shfl_xor_sync(0xffffffffu, l1, 1);
    l1 += __shfl_xor_sync(0xffffffffu, l1, 2);
    float inv0 = 1.f / l0, inv1 = 1.f / l1;

    size_t ga = ((size_t)(bb * S_) + rowa) * DMODEL + hh * DH;
    size_t gb = ga + (size_t)8 * DMODEL;
#pragma unroll
    for (int i = 0; i < 16; i++) {
        int d = i * 8 + 2 * (lane & 3);
        *(uint32_t*)(aoh + ga + d) = pack_h2(of[i][0] * inv0, of[i][1] * inv0);
        *(uint32_t*)(aoh + gb + d) = pack_h2(of[i][2] * inv1, of[i][3] * inv1);
    }
}

// ---------------- merged LayerNorm ----------------
__global__ __launch_bounds__(256)
void layernorm2(const float* __restrict__ p1,
                h16* __restrict__ cqh,
                float* __restrict__ ckv,
                h16* __restrict__ ckvh,
                const float* __restrict__ q_w, const float* __restrict__ q_b,
                const float* __restrict__ kv_w, const float* __restrict__ kv_b)
{
    bool isKV = blockIdx.y != 0;
    const float* p = p1 + (size_t)blockIdx.x * N1 + (isKV ? QPROJ : 0);
    int n = isKV ? KVPROJ : QPROJ;
    int npad = isKV ? KVPAD : QPROJ;
    const float* w = isKV ? kv_w : q_w;
    const float* b = isKV ? kv_b : q_b;
    h16* hh = (isKV ? ckvh : cqh) + (size_t)blockIdx.x * npad;
    float* of = isKV ? ckv + (size_t)blockIdx.x * KVPROJ : nullptr;

    float s = 0.f, s2 = 0.f;
    for (int j = threadIdx.x; j < n; j += 256) {
        float v = p[j];
        s += v; s2 += v * v;
    }
    __shared__ float sh[20];
#pragma unroll
    for (int o = 16; o; o >>= 1) {
        s  += __shfl_down_sync(0xffffffffu, s,  o);
        s2 += __shfl_down_sync(0xffffffffu, s2, o);
    }
    int wd = threadIdx.x >> 5, ln = threadIdx.x & 31;
    if (!ln) { sh[wd] = s; sh[wd + 8] = s2; }
    __syncthreads();
    if (threadIdx.x == 0) {
        float ts = 0.f, ts2 = 0.f;
        for (int i = 0; i < 8; i++) { ts += sh[i]; ts2 += sh[i + 8]; }
        float mean = ts / n;
        float var = fmaxf(ts2 / n - mean * mean, 0.f);
        sh[16] = mean;
        sh[17] = rsqrtf(var + 1e-5f);
    }
    __syncthreads();
    float mean = sh[16], rstd = sh[17];
    for (int j = threadIdx.x; j < npad; j += 256) {
        float v = 0.f;
        if (j < n) {
            v = (p[j] - mean) * rstd * w[j] + b[j];
            if (of) of[j] = v;
        }
        hh[j] = __float2half_rn(v);
    }
}

// ---------------- launch ----------------
static inline void* sym(const void* s) { void* p; cudaGetSymbolAddress(&p, s); return p; }

extern "C" void kernel_launch(void* const* d_in, const int* in_sizes, int n_in,
                              void* d_out, int out_size)
{
    const float* x     = (const float*)d_in[0];
    const float* W_dq  = (const float*)d_in[1];
    const float* W_uq  = (const float*)d_in[2];
    const float* W_qr  = (const float*)d_in[3];
    const float* W_dkv = (const float*)d_in[4];
    const float* W_ukv = (const float*)d_in[5];
    const float* W_kr  = (const float*)d_in[6];
    const float* W_o   = (const float*)d_in[7];
    const float* q_w   = (const float*)d_in[8];
    const float* q_b   = (const float*)d_in[9];
    const float* kv_w  = (const float*)d_in[10];
    const float* kv_b  = (const float*)d_in[11];

    float* out = (float*)d_out;
    float* ckv = out + (size_t)BS * DMODEL;

    h16 *xhi=(h16*)sym(g_xhi);
    h16 *w1h=(h16*)sym(g_w1h);
    h16 *w2h=(h16*)sym(g_w2h);
    h16 *wukvh=(h16*)sym(g_wukvh);
    h16 *woh=(h16*)sym(g_woh);
    float *p1=(float*)sym(g_p1);
    h16 *cqh=(h16*)sym(g_cqh);
    h16 *ckvh=(h16*)sym(g_ckvh);
    h16 *q2h=(h16*)sym(g_q2h);
    h16 *kvh=(h16*)sym(g_kvh);
    h16 *aoh=(h16*)sym(g_aoh);

    cudaFuncSetAttribute(hmma_gemm1, cudaFuncAttributeMaxDynamicSharedMemorySize, SMEM_GEMM);
    cudaFuncSetAttribute(hmma_gemm_dual, cudaFuncAttributeMaxDynamicSharedMemorySize, SMEM_GEMM);
    cudaFuncSetAttribute(gemm_p1_prep2, cudaFuncAttributeMaxDynamicSharedMemorySize, SMEM_GEMM);
    cudaFuncSetAttribute(flash_attn, cudaFuncAttributeMaxDynamicSharedMemorySize, SMEM_FLASH);

    // 1. x convert + W1 transposes
    prep1<<<1216, 256>>>(x, W_dq, W_dkv, W_kr, xhi, w1h);

    // 2. p1 = x @ W1 (fp32) fused with prep2
    gemm_p1_prep2<<<1844, 256, SMEM_GEMM>>>(
        xhi, w1h, p1,
        W_uq, W_qr, W_ukv, W_o,
        w2h, wukvh, woh);

    // 3. LayerNorms (merged)
    layernorm2<<<dim3(BS, 2), 256>>>(p1, cqh, ckv, ckvh, q_w, q_b, kv_w, kv_b);

    // 4. q2 + ukv GEMMs + rope-K in one launch
    {
        int gx_ukv = KVCOLS / 128;              // 30
        int gx_q2  = N2 / 128;                  // 16
        int blocks_ukv = gx_ukv * (BS / 128);   // 960
        int blocks_q2  = gx_q2  * (BS / 128);   // 512
        int total_gemm = blocks_ukv + blocks_q2;
        hmma_gemm_dual<<<total_gemm + 256, 256, SMEM_GEMM>>>(
            ckvh, wukvh, kvh,
            KVCOLS, KVPAD, KVPAD, KVPAD, KVLD, gx_ukv,
            cqh, w2h, q2h,
            N2, QPROJ, QPROJ, QPROJ, N2, gx_q2,
            blocks_ukv, total_gemm,
            p1, kvh);
    }

    // 5. flash attention (rope-Q fused in prologue)
    flash_attn<<<dim3(S_/128, NZ), 256, SMEM_FLASH>>>(q2h, kvh, aoh);

    // 6. final projection
    hmma_gemm1<<<dim3(DMODEL/128, BS/128), 256, SMEM_GEMM>>>(
        aoh, woh, out, DMODEL, DMODEL, DMODEL, DMODEL, DMODEL);
}